// round 16
// baseline (speedup 1.0000x reference)
#include <cuda_runtime.h>
#include <cuda_fp16.h>
#include <cstdint>

// Problem constants
#define B_   8
#define N_   2048
#define F0_  128
#define HID_ 64
#define OUT_ 16
#define K_   10

#define FBLK 128                 // filter blocks: 16 w-columns each, full 2048 rows
#define HBLK 128                 // hf blocks: 2 (b,chunk) assignments each
#define TPB  256
#define SLOTSTRIDE 520           // half2 words per slot group (64*8 + 8 pad)
#define DYNSMEM (32 * SLOTSTRIDE * 4)   // 66560 B

// ---------------- device scratch (static; no allocation) ----------------
__device__ float2 g_zr[K_ + 1][N_];          // (z_j, r_j) interleaved, per pass
__device__ float g_part[B_][32][HID_];       // per-(b,chunk) weighted partials
__device__ unsigned g_cnt[8 * 32];           // 8 group counters, 128B apart
__device__ unsigned g_hfdone = 0;            // monotonic hf completion counter

__constant__ float c_binom[K_ + 1] = {1.f, 10.f, 45.f, 120.f, 210.f, 252.f,
                                      210.f, 120.f, 45.f, 10.f, 1.f};

__device__ __forceinline__ void wait_cnt(volatile unsigned* ctr, unsigned target) {
    int spins = 0;
    while (*ctr < target) {
        if (++spins > 64) __nanosleep(32);
    }
    __threadfence();
}

__global__ __launch_bounds__(TPB) void mega_kernel(
    const float* __restrict__ X,  const float* __restrict__ L,
    const float* __restrict__ W1, const float* __restrict__ b1,
    const float* __restrict__ W2, const float* __restrict__ b2,
    const float* __restrict__ theta, float* __restrict__ out)
{
    extern __shared__ char dynsmem[];            // 65 KB: L-stripe or W1
    __half2* tile = reinterpret_cast<__half2*>(dynsmem);   // filter stripe
    float*   w1s  = reinterpret_cast<float*>(dynsmem);     // hf: W1

    __shared__ float2 szr[N_];           // full (z,r)_{j-1} (16 KB)
    __shared__ float4 redd[32][8];       // slot partials (az0,az1,ar0,ar1)
    __shared__ float redc[64][17];       // convert-phase column-sum partials
    __shared__ float b1s[HID_];
    __shared__ float redh[8][16];
    __shared__ float hg[B_ * HID_];
    __shared__ unsigned sbase[8];
    __shared__ unsigned shb;

    const int tid = threadIdx.x;
    const int bid = blockIdx.x;

    if (bid < FBLK) {
        // =================== FILTER BLOCKS (column stripes) ===============
        // snapshot counter bases at entry (monotonic; first arrival needs
        // the ~3us convert phase, snapshots land within ~100ns)
        if (tid < 8) sbase[tid] = *((volatile unsigned*)&g_cnt[tid * 32]);
        if (bid == 0 && tid == 0) shb = *((volatile unsigned*)&g_hfdone);

        // ---- Phase 0: convert stripe to fp16 AND accumulate column sums
        //      (fused pass 1: z0 = 1, r0 = a_K -> L^T z0 = colsum)
        const int w0 = bid * 16;
        {
            const int q  = tid & 3;          // float4 within row
            const int r0 = tid >> 2;         // row base
            float cs0 = 0.f, cs1 = 0.f, cs2 = 0.f, cs3 = 0.f;
#pragma unroll 4
            for (int g = 0; g < 32; ++g) {
                int v = g * 64 + r0;
                float4 f = *reinterpret_cast<const float4*>(
                    L + (size_t)v * N_ + w0 + q * 4);
                int off = (v & 31) * SLOTSTRIDE + (v >> 5) * 8 + q * 2;
                tile[off]     = __floats2half2_rn(f.x, f.y);
                tile[off + 1] = __floats2half2_rn(f.z, f.w);
                cs0 += f.x; cs1 += f.y; cs2 += f.z; cs3 += f.w;
            }
            redc[r0][q * 4 + 0] = cs0;
            redc[r0][q * 4 + 1] = cs1;
            redc[r0][q * 4 + 2] = cs2;
            redc[r0][q * 4 + 3] = cs3;
        }
        __syncthreads();
        if (tid < 16) {                      // finish pass 1 for my 16 w
            float zs = 0.f;
#pragma unroll
            for (int r = 0; r < 64; ++r) zs += redc[r][tid];
            float z1 = 1.0f - zs;
            float aK   = theta[K_];                          // a_K (binom=1)
            float aKm1 = theta[K_ - 1] * c_binom[K_ - 1];
            g_zr[1][w0 + tid] = make_float2(z1, aK * zs + aKm1 * z1);
        }
        __syncthreads();
        if (tid == 0) {                      // arrival #1 (pass 1 done)
            __threadfence();
            atomicAdd(&g_cnt[(bid & 7) * 32], 1u);
        }

        const int c = tid & 7;               // half2 column (w = w0+2c, +1)
        const int s = tid >> 3;              // slot 0..31 (v ≡ s mod 32)

        // ---- Passes 2..K -------------------------------------------------
        for (int j = 2; j <= K_; ++j) {
            if (tid < 8)                     // all groups wrote pass j-1
                wait_cnt((volatile unsigned*)&g_cnt[tid * 32],
                         sbase[tid] + 16u * (unsigned)(j - 1));
            __syncthreads();
            for (int i = tid; i < N_ / 2; i += TPB)     // stage 16 KB zr
                reinterpret_cast<float4*>(szr)[i] =
                    reinterpret_cast<const float4*>(g_zr[j - 1])[i];
            __syncthreads();

            // full-column dot: v = it*32 + s (conflict-free by layout)
            float az0 = 0.f, az1 = 0.f, ar0 = 0.f, ar1 = 0.f;
#pragma unroll
            for (int it = 0; it < 64; ++it) {
                int v = it * 32 + s;
                float2 f = __half22float2(tile[s * SLOTSTRIDE + it * 8 + c]);
                float2 zr = szr[v];
                az0 += f.x * zr.x;  az1 += f.y * zr.x;
                ar0 += f.x * zr.y;  ar1 += f.y * zr.y;
            }
            redd[s][c] = make_float4(az0, az1, ar0, ar1);
            __syncthreads();

            if (tid < 16) {                  // 16 outputs: in-block reduce
                int cc = tid >> 1, e = tid & 1;
                float zs = 0.f, rs = 0.f;
#pragma unroll
                for (int g = 0; g < 32; ++g) {
                    float4 p = redd[g][cc];
                    zs += e ? p.y : p.x;
                    rs += e ? p.w : p.z;
                }
                int w = w0 + 2 * cc + e;
                float znew = szr[w].x - zs;
                float aj = theta[K_ - j] * c_binom[K_ - j];
                g_zr[j][w] = make_float2(znew, rs + aj * znew);
            }
            __syncthreads();
            if (tid == 0) {                  // arrive on my group counter
                __threadfence();
                atomicAdd(&g_cnt[(bid & 7) * 32], 1u);
            }
        }

        // ---- block 0: wait for hf partials, emit logits -----------------
        if (bid == 0) {
            if (tid == 0) {
                unsigned target = shb + (unsigned)HBLK;
                int spins = 0;
                while (*((volatile unsigned*)&g_hfdone) < target) {
                    if (++spins > 16) __nanosleep(64);
                }
                __threadfence();
            }
            __syncthreads();

            for (int i = tid; i < B_ * HID_; i += TPB) {
                int bb = i >> 6, hh = i & 63;
                float sacc = 0.f;
#pragma unroll
                for (int ck = 0; ck < 32; ++ck) sacc += g_part[bb][ck][hh];
                hg[i] = sacc;
            }
            __syncthreads();
            if (tid < B_ * OUT_) {           // 128 threads = 8 x 16
                int bb = tid >> 4, o = tid & 15;
                float acc = b2[o];
#pragma unroll
                for (int hh = 0; hh < HID_; ++hh)
                    acc += hg[bb * HID_ + hh] * W2[hh * OUT_ + o];
                out[bb * OUT_ + o] = acc;
            }
        }
    } else {
        // =================== HF BLOCKS (overlap with filter) ==============
        const int hb = bid - FBLK;           // 0..127
        const int b = hb >> 4;               // batch
        const int c0 = (2 * hb) & 31;        // first of my two chunks

        if (tid < 8) sbase[tid] = *((volatile unsigned*)&g_cnt[tid * 32]);

        for (int i = tid; i < F0_ * HID_; i += TPB) w1s[i] = W1[i];
        if (tid < HID_) b1s[tid] = b1[tid];
        __syncthreads();

        const int tx = tid & 63;             // row within chunk
        const int ty = tid >> 6;             // 0..3 -> 16 hid each
        const int h0 = ty * 16;

        float acc[2][16];
#pragma unroll
        for (int a = 0; a < 2; ++a)
#pragma unroll
            for (int h = 0; h < 16; ++h) acc[a][h] = b1s[h0 + h];

#pragma unroll
        for (int a = 0; a < 2; ++a) {
            const int n = (c0 + a) * 64 + tx;
            const float* xr = X + ((size_t)b * N_ + n) * F0_;
            for (int f0 = 0; f0 < F0_; f0 += 16) {
                float4 xv[4];
#pragma unroll
                for (int i = 0; i < 4; ++i)
                    xv[i] = reinterpret_cast<const float4*>(xr + f0)[i];
                const float* xf = reinterpret_cast<const float*>(xv);
#pragma unroll
                for (int i = 0; i < 16; ++i) {
                    float x = xf[i];
                    const float4* wrow =
                        reinterpret_cast<const float4*>(&w1s[(f0 + i) * HID_ + h0]);
#pragma unroll
                    for (int q = 0; q < 4; ++q) {
                        float4 wv = wrow[q];
                        acc[a][q * 4 + 0] += x * wv.x;
                        acc[a][q * 4 + 1] += x * wv.y;
                        acc[a][q * 4 + 2] += x * wv.z;
                        acc[a][q * 4 + 3] += x * wv.w;
                    }
                }
            }
        }

        // ---- wait: filter chain done (all groups through pass K) --------
        if (tid < 8)
            wait_cnt((volatile unsigned*)&g_cnt[tid * 32],
                     sbase[tid] + 16u * (unsigned)K_);
        __syncthreads();

        const float invN = 1.0f / (float)N_;
        const int lane = tid & 31, warp = tid >> 5;
#pragma unroll
        for (int a = 0; a < 2; ++a) {
            const int chunk = c0 + a;
            float vn = g_zr[K_][chunk * 64 + tx].y * invN;   // v[n]/N
#pragma unroll
            for (int h = 0; h < 16; ++h) {
                float val = fmaxf(acc[a][h], 0.f) * vn;
                val += __shfl_xor_sync(0xffffffffu, val, 16);
                val += __shfl_xor_sync(0xffffffffu, val, 8);
                val += __shfl_xor_sync(0xffffffffu, val, 4);
                val += __shfl_xor_sync(0xffffffffu, val, 2);
                val += __shfl_xor_sync(0xffffffffu, val, 1);
                acc[a][h] = val;
            }
            if (lane == 0) {
#pragma unroll
                for (int h = 0; h < 16; ++h) redh[warp][h] = acc[a][h];
            }
            __syncthreads();
            if (tid < 64) {
                int g = tid >> 4, hh = tid & 15;
                g_part[b][chunk][g * 16 + hh] =
                    redh[2 * g][hh] + redh[2 * g + 1][hh];
            }
            __syncthreads();
        }

        if (tid == 0) {
            __threadfence();
            atomicAdd(&g_hfdone, 1u);
        }
    }
}

// ---------------- launcher ----------------------------------------------
extern "C" void kernel_launch(void* const* d_in, const int* in_sizes, int n_in,
                              void* d_out, int out_size) {
    const float* X     = (const float*)d_in[0];
    const float* L     = (const float*)d_in[1];
    const float* W1    = (const float*)d_in[2];
    const float* b1    = (const float*)d_in[3];
    const float* W2    = (const float*)d_in[4];
    const float* b2    = (const float*)d_in[5];
    const float* theta = (const float*)d_in[6];
    float* out = (float*)d_out;

    cudaFuncSetAttribute(mega_kernel,
                         cudaFuncAttributeMaxDynamicSharedMemorySize, DYNSMEM);
    mega_kernel<<<FBLK + HBLK, TPB, DYNSMEM>>>(X, L, W1, b1, W2, b2, theta, out);
}